// round 5
// baseline (speedup 1.0000x reference)
#include <cuda_runtime.h>
#include <cuda_bf16.h>
#include <cstdint>

// Problem shape (fixed for this dataset entry)
#define B_  8
#define T_  256
#define U_  64
#define V_  1024
#define U1_ (U_ + 1)
#define NEGF   (-1e30f)
#define LOG2EF (1.4426950408889634f)
#define LN2F   (0.6931471805599453f)

// Scratch (allocation-free rule: __device__ globals)
__device__ float    g_blank[B_ * T_ * U1_];  // log2-domain lp[b,t,u,0]
__device__ float    g_emit [B_ * T_ * U_ ];  // log2-domain lp[b,t,u,label]
__device__ float    g_ll   [B_];
__device__ unsigned g_cnt;
__device__ unsigned g_done [B_ * T_];        // per-(b,t) completed-row counters

// Ring buffer: 80 t-rows staged in shared memory (window 66 + slack 14)
#define RING 80
#define SLACK (RING - 66)                    // 14
#define SB_STRIDE 66
#define S_BLANK_F (RING * SB_STRIDE)         // 5280 floats
#define S_EMIT_F  (RING * U_)                // 5120 floats
#define SMEM_BYTES ((S_BLANK_F + S_EMIT_F + 8) * 4)   // ~41.7 KB

__device__ __forceinline__ unsigned ld_acquire_gpu(const unsigned* p) {
    unsigned v;
    asm volatile("ld.acquire.gpu.global.u32 %0, [%1];" : "=r"(v) : "l"(p));
    return v;
}
__device__ __forceinline__ void red_release_add(unsigned* p, unsigned v) {
    asm volatile("red.release.gpu.global.add.u32 [%0], %1;" :: "l"(p), "r"(v) : "memory");
}
__device__ __forceinline__ float ex2_approx(float x) {
    float r; asm("ex2.approx.f32 %0, %1;" : "=f"(r) : "f"(x)); return r;
}
__device__ __forceinline__ float lg2_approx(float x) {
    float r; asm("lg2.approx.f32 %0, %1;" : "=f"(r) : "f"(x)); return r;
}
__device__ __forceinline__ float lae2(float x, float y) {
    const float M  = fmaxf(x, y);
    const float mn = fminf(x, y);
    return M + lg2_approx(1.f + ex2_approx(mn - M));
}

__global__ __launch_bounds__(256) void fused_kernel(
    const float* __restrict__ logits, const int* __restrict__ labels,
    const int* __restrict__ f_len,    const int* __restrict__ y_len,
    float* __restrict__ out)
{
    extern __shared__ float sm[];

    if (blockIdx.x >= B_) {
        // ================= LSE producer role =================
        const int warp = threadIdx.x >> 5;
        const int lane = threadIdx.x & 31;
        const int row  = (blockIdx.x - B_) * 8 + warp;   // 0..133119
        // t-major: all batches progress through t together
        const int t   = row / (B_ * U1_);
        const int rem = row % (B_ * U1_);
        const int b   = rem / U1_;
        const int u   = rem % U1_;
        const size_t goff = ((size_t)(b * T_ + t) * U1_ + u) * V_;

        const float4* p = reinterpret_cast<const float4*>(logits + goff);
        float4 v[8];
#pragma unroll
        for (int k = 0; k < 8; ++k) v[k] = p[k * 32 + lane];

        float m = v[0].x;
#pragma unroll
        for (int k = 0; k < 8; ++k) {
            m = fmaxf(m, v[k].x); m = fmaxf(m, v[k].y);
            m = fmaxf(m, v[k].z); m = fmaxf(m, v[k].w);
        }
        const float mloc = m;
        float s = 0.f;
#pragma unroll
        for (int k = 0; k < 8; ++k) {
            s += __expf(v[k].x - mloc); s += __expf(v[k].y - mloc);
            s += __expf(v[k].z - mloc); s += __expf(v[k].w - mloc);
        }
#pragma unroll
        for (int o = 16; o; o >>= 1) m = fmaxf(m, __shfl_xor_sync(0xffffffffu, m, o));
        s *= __expf(mloc - m);
#pragma unroll
        for (int o = 16; o; o >>= 1) s += __shfl_xor_sync(0xffffffffu, s, o);

        if (lane == 0) {
            const float lse = m + __logf(s);
            g_blank[(b * T_ + t) * U1_ + u] = (v[0].x - lse) * LOG2EF;
            if (u < U_) {
                const int lab = labels[b * U_ + u];
                const float lv = __ldg(logits + goff + lab);   // L1 hit
                g_emit[(b * T_ + t) * U_ + u] = (lv - lse) * LOG2EF;
            }
            red_release_add(&g_done[b * T_ + t], 1u);          // publish
        }
        return;
    }

    // ================= ALPHA consumer role (blocks 0..7) =================
    float* s_blank = sm;                       // ring [RING][66]
    float* s_emit  = sm + S_BLANK_F;           // ring [RING][64]
    volatile int* s_hi  = (volatile int*)(sm + S_BLANK_F + S_EMIT_F); // [2]
    volatile int* s_dpd = s_hi + 2;            // DP progress (backpressure)

    const int b    = blockIdx.x;
    const int tid  = threadIdx.x;
    const int warp = tid >> 5;
    const int lane = tid & 31;
    const int uy     = y_len[b];               // [32,64]
    const int t_last = f_len[b] - 1;           // [127,255]

    if (tid == 0) { s_hi[0] = -1; s_hi[1] = -1; *s_dpd = 0; }
    __syncthreads();
    if (warp > 2) return;

    const float* gb = g_blank + b * T_ * U1_;
    const float* ge = g_emit  + b * T_ * U_;
    unsigned*    gd = g_done  + b * T_;

    if (warp >= 1) {
        // -------- staging warps: warp1 = even t, warp2 = odd t --------
        const int par = warp - 1;
        for (int t = par; t < T_; t += 2) {
            if (lane == 0) {
                while (t > *s_dpd + SLACK) __nanosleep(100);       // ring backpressure
                while (ld_acquire_gpu(&gd[t]) < (unsigned)U1_) __nanosleep(60);
                gd[t] = 0;                                          // reset for next replay
            }
            __syncwarp();
            const int r = t % RING;
            const float b0 = gb[t * U1_ + lane];
            const float b1 = gb[t * U1_ + 32 + lane];
            const float e0 = ge[t * U_  + lane];
            const float e1 = ge[t * U_  + 32 + lane];
            s_blank[r * SB_STRIDE + lane]      = b0;
            s_blank[r * SB_STRIDE + 32 + lane] = b1;
            if (lane == 0) s_blank[r * SB_STRIDE + 64] = gb[t * U1_ + 64];
            s_emit[r * U_ + lane]      = (lane      < uy) ? e0 : NEGF;
            s_emit[r * U_ + 32 + lane] = (lane + 32 < uy) ? e1 : NEGF;
            asm volatile("membar.cta;" ::: "memory");
            if (lane == 0) s_hi[par] = t;                           // publish
        }
        return;
    }

    // -------- DP warp (warp 0): register wavefront over diagonals --------
    const int l = lane;
    float a0 = NEGF, a1 = NEGF, a2 = NEGF;
    const int d_end = t_last + uy;
    int tmax_loc = -1;

    for (int d = 0; d <= d_end; ++d) {
        const int needed_t = min(d, T_ - 1);
        if (needed_t > tmax_loc) {
            do {
                tmax_loc = min(s_hi[0], s_hi[1]);
            } while (tmax_loc < needed_t);
            asm volatile("membar.cta;" ::: "memory");
        }
        if (l == 0) *s_dpd = d;

        float L0 = __shfl_up_sync(0xffffffffu, a0, 1);
        float L1 = __shfl_up_sync(0xffffffffu, a1, 1);
        const float top0 = __shfl_sync(0xffffffffu, a0, 31);
        const float top1 = __shfl_sync(0xffffffffu, a1, 31);
        if (l == 0) { L0 = NEGF; L1 = top0; }
        const float L2 = top1;

        const int t0 = d - l;
        const int t1 = t0 - 32;
        const int t2 = d - 64;

        const int ct0  = min(max(t0, 0), T_ - 1) % RING;
        const int ct1  = min(max(t1, 0), T_ - 1) % RING;
        const int ct2  = min(max(t2, 0), T_ - 1) % RING;
        const int ct0m = max(t0 - 1, 0) % RING;
        const int ct1m = max(t1 - 1, 0) % RING;
        const int ct2m = max(t2 - 1, 0) % RING;

        float e0 = s_emit[ct0 * U_ + max(l - 1, 0)];
        if (l == 0) e0 = NEGF;
        const float e1 = s_emit[ct1 * U_ + (l + 31)];
        const float e2 = s_emit[ct2 * U_ + 63];

        float bl0 = s_blank[ct0m * SB_STRIDE + l];
        float bl1 = s_blank[ct1m * SB_STRIDE + l + 32];
        float bl2 = s_blank[ct2m * SB_STRIDE + 64];
        if (t0 < 1) bl0 = NEGF;
        if (t1 < 1) bl1 = NEGF;
        if (t2 < 1) bl2 = NEGF;

        float n0 = lae2(L0 + e0, a0 + bl0);
        float n1 = lae2(L1 + e1, a1 + bl1);
        float n2 = lae2(L2 + e2, a2 + bl2);
        if (l == 0 && d == 0) n0 = 0.f;          // alpha[0][0] = 0

        if (t0 >= 0 && t0 < T_) a0 = n0;
        if (t1 >= 0 && t1 < T_) a1 = n1;
        if (t2 >= 0 && t2 < T_) a2 = n2;
    }

    const float av = (uy == U_) ? a2 : __shfl_sync(0xffffffffu, a1, uy - 32);
    const float blT = s_blank[(t_last % RING) * SB_STRIDE + uy];
    if (l == 0) *s_dpd = 1 << 20;                // release staging fully

    if (l == 0) {
        g_ll[b] = (av + blT) * LN2F;
        __threadfence();
        const unsigned old = atomicAdd(&g_cnt, 1u);
        if (old == B_ - 1) {
            g_cnt = 0;                           // reset for next replay
            float s = 0.f;
#pragma unroll
            for (int i = 0; i < B_; ++i) s += ((volatile float*)g_ll)[i];
            out[0] = -s * (1.f / (float)B_);
        }
    }
}

extern "C" void kernel_launch(void* const* d_in, const int* in_sizes, int n_in,
                              void* d_out, int out_size)
{
    const float* logits = (const float*)d_in[0];
    const int*   labels = (const int*)d_in[1];
    const int*   f_len  = (const int*)d_in[2];
    const int*   y_len  = (const int*)d_in[3];
    float* out = (float*)d_out;

    cudaFuncSetAttribute(fused_kernel,
                         cudaFuncAttributeMaxDynamicSharedMemorySize,
                         SMEM_BYTES);

    const int lse_blocks = (B_ * T_ * U1_) / 8;   // 16640
    fused_kernel<<<B_ + lse_blocks, 256, SMEM_BYTES>>>(
        logits, labels, f_len, y_len, out);
}

// round 7
// speedup vs baseline: 1.2605x; 1.2605x over previous
#include <cuda_runtime.h>
#include <cuda_bf16.h>
#include <cstdint>

// Problem shape (fixed for this dataset entry)
#define B_  8
#define T_  256
#define U_  64
#define V_  1024
#define U1_ (U_ + 1)
#define NEGF   (-1e30f)
#define LOG2EF (1.4426950408889634f)
#define LN2F   (0.6931471805599453f)

// Scratch (allocation-free rule: __device__ globals)
__device__ float    g_blank[B_ * T_ * U1_];  // log2-domain lp[b,t,u,0]
__device__ float    g_emit [B_ * T_ * U_ ];  // log2-domain lp[b,t,u,label]
__device__ float    g_ll   [B_];
__device__ unsigned g_cnt;

// ---------------------------------------------------------------------------
// Kernel 1: per-row logsumexp over V=1024 (identical structure to the proven
// 80.6us / 86%-DRAM version).
// ---------------------------------------------------------------------------
__global__ __launch_bounds__(256) void lse_kernel(
    const float* __restrict__ logits, const int* __restrict__ labels)
{
    const int warp = threadIdx.x >> 5;
    const int lane = threadIdx.x & 31;
    const int row  = blockIdx.x * 8 + warp;          // < B_*T_*U1_ = 133120

    const float4* p = reinterpret_cast<const float4*>(logits + (size_t)row * V_);

    float4 v[8];
#pragma unroll
    for (int k = 0; k < 8; ++k) v[k] = p[k * 32 + lane];

    float m = v[0].x;
#pragma unroll
    for (int k = 0; k < 8; ++k) {
        m = fmaxf(m, v[k].x); m = fmaxf(m, v[k].y);
        m = fmaxf(m, v[k].z); m = fmaxf(m, v[k].w);
    }
    const float mloc = m;

    float s = 0.f;
#pragma unroll
    for (int k = 0; k < 8; ++k) {
        s += __expf(v[k].x - mloc); s += __expf(v[k].y - mloc);
        s += __expf(v[k].z - mloc); s += __expf(v[k].w - mloc);
    }

#pragma unroll
    for (int o = 16; o; o >>= 1) m = fmaxf(m, __shfl_xor_sync(0xffffffffu, m, o));
    s *= __expf(mloc - m);
#pragma unroll
    for (int o = 16; o; o >>= 1) s += __shfl_xor_sync(0xffffffffu, s, o);

    if (lane == 0) {
        const float lse = m + __logf(s);
        const int u  = row % U1_;
        const int bt = row / U1_;
        const int t  = bt % T_;
        const int b  = bt / T_;
        g_blank[row] = (v[0].x - lse) * LOG2EF;
        if (u < U_) {
            const int lab = labels[b * U_ + u];
            const float lv = __ldg(logits + (size_t)row * V_ + lab);  // L1 hit
            g_emit[(b * T_ + t) * U_ + u] = (lv - lse) * LOG2EF;
        }
    }
}

// ---------------------------------------------------------------------------
// Kernel 2: register wavefront, three-phase (ramp / steady / ramp).
// Lane l owns u=l (a0), u=l+32 (a1); u=64 (a2) uniform across lanes.
// pe[t][u] = emit[t][u-1] (pe[t][0]=NEGF), stride 66 -> conflict-free and
// branchless left-edge handling.
// ---------------------------------------------------------------------------
#define STR 66
#define S_BF (T_ * STR)                      // 16896 floats (blank)
#define S_EF (T_ * STR)                      // 16896 floats (padded emit)
#define SMEM_BYTES ((S_BF + S_EF) * 4)       // 132 KB

__device__ __forceinline__ float ex2_approx(float x) {
    float r; asm("ex2.approx.f32 %0, %1;" : "=f"(r) : "f"(x)); return r;
}
__device__ __forceinline__ float lg2_approx(float x) {
    float r; asm("lg2.approx.f32 %0, %1;" : "=f"(r) : "f"(x)); return r;
}
__device__ __forceinline__ float lae2(float x, float y) {
    const float M  = fmaxf(x, y);
    const float mn = fminf(x, y);
    return M + lg2_approx(1.f + ex2_approx(mn - M));
}

__global__ __launch_bounds__(256) void alpha_kernel(
    const int* __restrict__ f_len, const int* __restrict__ y_len,
    float* __restrict__ out)
{
    extern __shared__ float sm[];
    float* sb = sm;                          // blank [256][66]
    float* se = sm + S_BF;                   // padded emit [256][66]

    const int b   = blockIdx.x;
    const int tid = threadIdx.x;             // 0..255
    const int uy     = y_len[b];             // [32,64]
    const int t_last = f_len[b] - 1;         // [127,255]

    const float* gb = g_blank + b * T_ * U1_;
    const float* ge = g_emit  + b * T_ * U_;

    // ---- fill (all 8 warps, linear strided: coalesced loads, high MLP) ----
    for (int i = tid; i < T_ * U_; i += 256) {           // emit -> pe[t][u+1]
        const int t = i >> 6, u = i & 63;
        se[t * STR + u + 1] = (u < uy) ? ge[i] : NEGF;
    }
    for (int t = tid; t < T_; t += 256) se[t * STR] = NEGF;   // pe[t][0]
    for (int i = tid; i < T_ * U1_; i += 256) {          // blank
        const int t = i / U1_, u = i % U1_;
        sb[t * STR + u] = gb[i];
    }
    __syncthreads();
    if (tid >= 32) return;                   // warps 1..7 done

    const int l = tid;
    float a0 = NEGF, a1 = NEGF, a2 = NEGF;
    const int d_end  = t_last + uy;          // [159,319]
    const int dB_end = min(d_end, T_ - 1);   // steady-state upper bound

    // ---------------- Phase A: d in [0,64] (ramp-in, clamped) -------------
    for (int d = 0; d <= 64; ++d) {
        float L0 = __shfl_up_sync(0xffffffffu, a0, 1);
        float L1 = __shfl_up_sync(0xffffffffu, a1, 1);
        const float top0 = __shfl_sync(0xffffffffu, a0, 31);
        const float top1 = __shfl_sync(0xffffffffu, a1, 31);
        if (l == 0) { L0 = NEGF; L1 = top0; }
        const float L2 = top1;

        const int t0 = d - l;
        const int t1 = t0 - 32;
        const int t2 = d - 64;
        const int ct0  = max(t0, 0);
        const int ct1  = max(t1, 0);
        const int ct0m = max(t0 - 1, 0);
        const int ct1m = max(t1 - 1, 0);

        const float e0 = se[ct0 * STR + l];            // pe[t0][l]
        const float e1 = se[ct1 * STR + l + 32];
        const float e2 = se[64];                       // pe[0][64] (only d=64)
        float bl0 = sb[ct0m * STR + l];
        float bl1 = sb[ct1m * STR + l + 32];
        if (t0 < 1) bl0 = NEGF;
        if (t1 < 1) bl1 = NEGF;
        const float bl2 = NEGF;                        // t2 <= 0 in phase A

        float n0 = lae2(L0 + e0, a0 + bl0);
        float n1 = lae2(L1 + e1, a1 + bl1);
        float n2 = lae2(L2 + e2, a2 + bl2);
        if (l == 0 && d == 0) n0 = 0.f;                // alpha[0][0] = 0

        if (t0 >= 0) a0 = n0;
        if (t1 >= 0) a1 = n1;
        if (t2 >= 0) a2 = n2;
    }

    // ------------- Phase B: d in [65, dB_end] (steady, no clamps) ---------
    {
        int eo = 66 * 65 - 65 * l;           // index of pe[t0][l] at d=65
        int du = 66 * 65;                    // uniform base 66*d
#pragma unroll 4
        for (int d = 65; d <= dB_end; ++d) {
            float L0 = __shfl_up_sync(0xffffffffu, a0, 1);
            float L1 = __shfl_up_sync(0xffffffffu, a1, 1);
            const float top0 = __shfl_sync(0xffffffffu, a0, 31);
            const float top1 = __shfl_sync(0xffffffffu, a1, 31);
            if (l == 0) L1 = top0;           // L0 fine: e0 = pe[t][0] = NEGF
            const float L2 = top1;

            const float e0  = se[eo];
            const float e1  = se[eo - 2080];
            const float e2  = se[du - 4160];
            const float bl0 = sb[eo - 66];
            const float bl1 = sb[eo - 2146];
            const float bl2 = sb[du - 4226];

            a0 = lae2(L0 + e0, a0 + bl0);
            a1 = lae2(L1 + e1, a1 + bl1);
            a2 = lae2(L2 + e2, a2 + bl2);

            eo += 66; du += 66;
        }
    }

    // ------------- Phase C: d in [256, d_end] (ramp-out, clamped) ---------
    for (int d = T_; d <= d_end; ++d) {
        float L0 = __shfl_up_sync(0xffffffffu, a0, 1);
        float L1 = __shfl_up_sync(0xffffffffu, a1, 1);
        const float top0 = __shfl_sync(0xffffffffu, a0, 31);
        const float top1 = __shfl_sync(0xffffffffu, a1, 31);
        if (l == 0) { L0 = NEGF; L1 = top0; }
        const float L2 = top1;

        const int t0 = d - l;                // >= 225
        const int t1 = t0 - 32;
        const int t2 = d - 64;               // [192,255] always valid
        const int ct0  = min(t0, T_ - 1);
        const int ct1  = min(t1, T_ - 1);
        const int ct0m = min(t0 - 1, T_ - 1);
        const int ct1m = min(t1 - 1, T_ - 1);

        const float e0  = se[ct0 * STR + l];
        const float e1  = se[ct1 * STR + l + 32];
        const float e2  = se[t2 * STR + 64];
        const float bl0 = sb[ct0m * STR + l];
        const float bl1 = sb[ct1m * STR + l + 32];
        const float bl2 = sb[(t2 - 1) * STR + 64];

        const float n0 = lae2(L0 + e0, a0 + bl0);
        const float n1 = lae2(L1 + e1, a1 + bl1);
        a2 = lae2(L2 + e2, a2 + bl2);
        if (t0 < T_) a0 = n0;
        if (t1 < T_) a1 = n1;
    }

    // ------------------------- readout + finalize -------------------------
    const float av  = (uy == U_) ? a2 : __shfl_sync(0xffffffffu, a1, uy - 32);
    const float blT = sb[t_last * STR + uy];

    if (l == 0) {
        g_ll[b] = (av + blT) * LN2F;
        __threadfence();
        const unsigned old = atomicAdd(&g_cnt, 1u);
        if (old == B_ - 1) {
            g_cnt = 0;                       // reset for next graph replay
            float s = 0.f;
#pragma unroll
            for (int i = 0; i < B_; ++i) s += ((volatile float*)g_ll)[i];
            out[0] = -s * (1.f / (float)B_);
        }
    }
}

extern "C" void kernel_launch(void* const* d_in, const int* in_sizes, int n_in,
                              void* d_out, int out_size)
{
    const float* logits = (const float*)d_in[0];
    const int*   labels = (const int*)d_in[1];
    const int*   f_len  = (const int*)d_in[2];
    const int*   y_len  = (const int*)d_in[3];
    float* out = (float*)d_out;

    cudaFuncSetAttribute(alpha_kernel,
                         cudaFuncAttributeMaxDynamicSharedMemorySize,
                         SMEM_BYTES);

    const int rows = B_ * T_ * U1_;          // 133120
    lse_kernel<<<rows / 8, 256>>>(logits, labels);
    alpha_kernel<<<B_, 256, SMEM_BYTES>>>(f_len, y_len, out);
}